// round 6
// baseline (speedup 1.0000x reference)
#include <cuda_runtime.h>

// Problem-shape maxima (compile-time array sizing; runtime uses in_sizes)
#define N1MAX 50000
#define NPMAX 200000
#define H2 32

// ---------------- scratch (static __device__, no allocation) ----------------
__device__ int   g_cnt1 [N1MAX];
__device__ int   g_cnt2f[NPMAX];
__device__ int   g_cnt2b[NPMAX];
__device__ float g_dinv1[N1MAX];
__device__ float g_dinvf[NPMAX];
__device__ float g_dinvb[NPMAX];
__device__ __align__(16) float g_y1  [N1MAX * H2];   // xw1 * dinv1[src], conv1 messages
__device__ __align__(16) float g_out1[N1MAX * H2];   // conv1 accumulator
__device__ __align__(16) float g_ya  [NPMAX * H2];   // xwa * dinvf[src]
__device__ __align__(16) float g_yb  [NPMAX * H2];   // xwb * dinvb[src]
__device__ __align__(16) float g_outa[NPMAX * H2];
__device__ __align__(16) float g_outb[NPMAX * H2];

__device__ __forceinline__ void red_add_v4(float* addr, float4 v) {
    asm volatile("red.global.add.v4.f32 [%0], {%1,%2,%3,%4};"
                 :: "l"(addr), "f"(v.x), "f"(v.y), "f"(v.z), "f"(v.w)
                 : "memory");
}

// ---------------- 1. zero degree counters ----------------
__global__ void k_zero(int n1, int np) {
    int i = blockIdx.x * blockDim.x + threadIdx.x;
    if (i < np) { g_cnt2f[i] = 0; g_cnt2b[i] = 0; }
    if (i < n1) { g_cnt1[i] = 0; }
}

// ---------------- 2. degree counting (all three graphs in one pass) --------
__global__ void k_count(const int* __restrict__ e1, const int* __restrict__ e2,
                        int E1, int E2) {
    int i = blockIdx.x * blockDim.x + threadIdx.x;
    if (i < E1) atomicAdd(&g_cnt1[e1[E1 + i]], 1);          // conv1 dst = edge1[1]
    if (i < E2) {
        atomicAdd(&g_cnt2f[e2[E2 + i]], 1);                  // conv2a dst = ei2[1]
        atomicAdd(&g_cnt2b[e2[i]],      1);                  // conv2b dst = ei2[0]
    }
}

// ---------------- 3. rsqrt degrees (deg = count + 1 self-loop) --------------
__global__ void k_dinv(int n1, int np) {
    int i = blockIdx.x * blockDim.x + threadIdx.x;
    if (i < np) {
        g_dinvf[i] = rsqrtf((float)(g_cnt2f[i] + 1));
        g_dinvb[i] = rsqrtf((float)(g_cnt2b[i] + 1));
    }
    if (i < n1) g_dinv1[i] = rsqrtf((float)(g_cnt1[i] + 1));
}

// ---------------- 4. embed gather + GEMM (256->32), write y1 and out1 init --
// Block = 128 threads (4 warps). Each warp computes 4 nodes (W1 reuse).
// smem: W1 (32 KB) + 4 warps * 4 rows * 1 KB (16 KB) = 48 KB exactly.
__global__ __launch_bounds__(128) void k_embed(
    const int* __restrict__ x, const float* __restrict__ emb,
    const float* __restrict__ W1, const float* __restrict__ b1, int n1)
{
    __shared__ float  W1s[256 * 32];
    __shared__ float4 rows[4][4][64];
    int tid = threadIdx.x;
    for (int i = tid; i < 256 * 32; i += 128) W1s[i] = W1[i];
    __syncthreads();

    int w = tid >> 5, lane = tid & 31;
    int base = (blockIdx.x * 4 + w) * 4;

    #pragma unroll
    for (int m = 0; m < 4; m++) {
        int n = base + m;
        if (n < n1) {
            const float4* src = reinterpret_cast<const float4*>(emb) + (size_t)x[n] * 64;
            rows[w][m][lane]      = src[lane];
            rows[w][m][lane + 32] = src[lane + 32];
        }
    }
    __syncwarp();

    float acc0 = 0.f, acc1 = 0.f, acc2 = 0.f, acc3 = 0.f;
    #pragma unroll 8
    for (int k4 = 0; k4 < 64; k4++) {
        float w0 = W1s[(k4 * 4 + 0) * 32 + lane];
        float w1 = W1s[(k4 * 4 + 1) * 32 + lane];
        float w2 = W1s[(k4 * 4 + 2) * 32 + lane];
        float w3 = W1s[(k4 * 4 + 3) * 32 + lane];
        float4 a;
        a = rows[w][0][k4]; acc0 += a.x*w0 + a.y*w1 + a.z*w2 + a.w*w3;
        a = rows[w][1][k4]; acc1 += a.x*w0 + a.y*w1 + a.z*w2 + a.w*w3;
        a = rows[w][2][k4]; acc2 += a.x*w0 + a.y*w1 + a.z*w2 + a.w*w3;
        a = rows[w][3][k4]; acc3 += a.x*w0 + a.y*w1 + a.z*w2 + a.w*w3;
    }

    float bj = __ldg(&b1[lane]);
    float accs[4] = {acc0, acc1, acc2, acc3};
    #pragma unroll
    for (int m = 0; m < 4; m++) {
        int n = base + m;
        if (n < n1) {
            float dv = g_dinv1[n];
            float y  = accs[m] * dv;
            g_y1  [n * 32 + lane] = y;                 // pre-scaled by dinv[src]
            g_out1[n * 32 + lane] = y * dv + bj;       // self-loop + bias init
        }
    }
}

// ---------------- 5. conv1 edge scatter: 8 threads per edge, red.v4 ---------
__global__ void k_scatter1(const int* __restrict__ e1, int E1) {
    int tid = blockIdx.x * 256 + threadIdx.x;
    int e = tid >> 3, t = tid & 7;
    if (e >= E1) return;
    int s = e1[e], d = e1[E1 + e];
    float dv = g_dinv1[d];
    float4 y = *reinterpret_cast<const float4*>(&g_y1[s * 32 + t * 4]);
    red_add_v4(&g_out1[d * 32 + t * 4],
               make_float4(y.x * dv, y.y * dv, y.z * dv, y.w * dv));
}

// ---------------- 6. pair gather-multiply + fused 32x32 GEMVs ---------------
// 8 threads per pair; hp row held in distributed float4, broadcast via shfl.
__global__ __launch_bounds__(256) void k_pair(
    const int* __restrict__ pos,
    const float* __restrict__ W2a, const float* __restrict__ b2a,
    const float* __restrict__ W2b, const float* __restrict__ b2b, int np)
{
    __shared__ __align__(16) float Was[1024];
    __shared__ __align__(16) float Wbs[1024];
    int tid = threadIdx.x;
    for (int i = tid; i < 1024; i += 256) { Was[i] = W2a[i]; Wbs[i] = W2b[i]; }
    __syncthreads();

    int g = blockIdx.x * 256 + tid;
    int m = g >> 3, t = g & 7;
    bool ok = (m < np);
    int p0 = 0, p1 = 0;
    if (ok) { p0 = pos[2 * m]; p1 = pos[2 * m + 1]; }

    float4 h0 = *reinterpret_cast<const float4*>(&g_out1[p0 * 32 + t * 4]);
    float4 h1 = *reinterpret_cast<const float4*>(&g_out1[p1 * 32 + t * 4]);
    float4 hp;
    hp.x = fmaxf(h0.x, 0.f) * fmaxf(h1.x, 0.f);
    hp.y = fmaxf(h0.y, 0.f) * fmaxf(h1.y, 0.f);
    hp.z = fmaxf(h0.z, 0.f) * fmaxf(h1.z, 0.f);
    hp.w = fmaxf(h0.w, 0.f) * fmaxf(h1.w, 0.f);

    float4 aa = make_float4(0.f, 0.f, 0.f, 0.f);
    float4 ab = make_float4(0.f, 0.f, 0.f, 0.f);
    #pragma unroll
    for (int src = 0; src < 8; src++) {
        float hv[4];
        hv[0] = __shfl_sync(0xffffffffu, hp.x, src, 8);
        hv[1] = __shfl_sync(0xffffffffu, hp.y, src, 8);
        hv[2] = __shfl_sync(0xffffffffu, hp.z, src, 8);
        hv[3] = __shfl_sync(0xffffffffu, hp.w, src, 8);
        #pragma unroll
        for (int kk = 0; kk < 4; kk++) {
            int k = src * 4 + kk;
            float4 wa = *reinterpret_cast<const float4*>(&Was[k * 32 + t * 4]);
            float4 wb = *reinterpret_cast<const float4*>(&Wbs[k * 32 + t * 4]);
            aa.x += hv[kk] * wa.x; aa.y += hv[kk] * wa.y;
            aa.z += hv[kk] * wa.z; aa.w += hv[kk] * wa.w;
            ab.x += hv[kk] * wb.x; ab.y += hv[kk] * wb.y;
            ab.z += hv[kk] * wb.z; ab.w += hv[kk] * wb.w;
        }
    }

    if (ok) {
        float da = g_dinvf[m], db = g_dinvb[m];
        float4 ba4 = *reinterpret_cast<const float4*>(&b2a[t * 4]);
        float4 bb4 = *reinterpret_cast<const float4*>(&b2b[t * 4]);
        float4 ya = make_float4(aa.x * da, aa.y * da, aa.z * da, aa.w * da);
        float4 yb = make_float4(ab.x * db, ab.y * db, ab.z * db, ab.w * db);
        *reinterpret_cast<float4*>(&g_ya[m * 32 + t * 4]) = ya;
        *reinterpret_cast<float4*>(&g_yb[m * 32 + t * 4]) = yb;
        *reinterpret_cast<float4*>(&g_outa[m * 32 + t * 4]) =
            make_float4(ya.x * da + ba4.x, ya.y * da + ba4.y,
                        ya.z * da + ba4.z, ya.w * da + ba4.w);
        *reinterpret_cast<float4*>(&g_outb[m * 32 + t * 4]) =
            make_float4(yb.x * db + bb4.x, yb.y * db + bb4.y,
                        yb.z * db + bb4.z, yb.w * db + bb4.w);
    }
}

// ---------------- 7. conv2 (fwd + reversed) edge scatter --------------------
__global__ void k_scatter2(const int* __restrict__ e2, int E2) {
    int tid = blockIdx.x * 256 + threadIdx.x;
    int e = tid >> 3, t = tid & 7;
    if (e >= E2) return;
    int u = e2[e], v = e2[E2 + e];
    // conv2a: src=u, dst=v (deg over ei2[1])
    float dvf = g_dinvf[v];
    float4 ya = *reinterpret_cast<const float4*>(&g_ya[u * 32 + t * 4]);
    red_add_v4(&g_outa[v * 32 + t * 4],
               make_float4(ya.x * dvf, ya.y * dvf, ya.z * dvf, ya.w * dvf));
    // conv2b: src=v, dst=u (deg over ei2[0])
    float dub = g_dinvb[u];
    float4 yb = *reinterpret_cast<const float4*>(&g_yb[v * 32 + t * 4]);
    red_add_v4(&g_outb[u * 32 + t * 4],
               make_float4(yb.x * dub, yb.y * dub, yb.z * dub, yb.w * dub));
}

// ---------------- 8. final: gather idx, even*odd, dot with Wp ---------------
__global__ void k_final(const int* __restrict__ idx,
                        const float* __restrict__ Wp, const float* __restrict__ bp,
                        float* __restrict__ out, int Q)
{
    int tid = blockIdx.x * 256 + threadIdx.x;
    int q = tid >> 3, t = tid & 7;
    bool ok = (q < Q);
    int i0 = 0, i1 = 0;
    if (ok) { i0 = idx[2 * q]; i1 = idx[2 * q + 1]; }

    float4 a0 = *reinterpret_cast<const float4*>(&g_outa[i0 * 32 + t * 4]);
    float4 b0 = *reinterpret_cast<const float4*>(&g_outb[i0 * 32 + t * 4]);
    float4 a1 = *reinterpret_cast<const float4*>(&g_outa[i1 * 32 + t * 4]);
    float4 b1 = *reinterpret_cast<const float4*>(&g_outb[i1 * 32 + t * 4]);

    float4 h0, h1;
    h0.x = fmaxf(a0.x, 0.f) + fmaxf(b0.x, 0.f);
    h0.y = fmaxf(a0.y, 0.f) + fmaxf(b0.y, 0.f);
    h0.z = fmaxf(a0.z, 0.f) + fmaxf(b0.z, 0.f);
    h0.w = fmaxf(a0.w, 0.f) + fmaxf(b0.w, 0.f);
    h1.x = fmaxf(a1.x, 0.f) + fmaxf(b1.x, 0.f);
    h1.y = fmaxf(a1.y, 0.f) + fmaxf(b1.y, 0.f);
    h1.z = fmaxf(a1.z, 0.f) + fmaxf(b1.z, 0.f);
    h1.w = fmaxf(a1.w, 0.f) + fmaxf(b1.w, 0.f);

    float4 wp4 = *reinterpret_cast<const float4*>(&Wp[t * 4]);
    float s = h0.x * h1.x * wp4.x + h0.y * h1.y * wp4.y
            + h0.z * h1.z * wp4.z + h0.w * h1.w * wp4.w;
    s += __shfl_xor_sync(0xffffffffu, s, 1, 8);
    s += __shfl_xor_sync(0xffffffffu, s, 2, 8);
    s += __shfl_xor_sync(0xffffffffu, s, 4, 8);
    if (ok && t == 0) out[q] = s + __ldg(bp);
}

// ---------------- launch ----------------------------------------------------
extern "C" void kernel_launch(void* const* d_in, const int* in_sizes, int n_in,
                              void* d_out, int out_size) {
    const int*   x    = (const int*)  d_in[0];
    const int*   e1   = (const int*)  d_in[1];
    const int*   pos  = (const int*)  d_in[2];
    const int*   idx  = (const int*)  d_in[3];
    const int*   e2   = (const int*)  d_in[4];
    const float* emb  = (const float*)d_in[5];
    const float* W1   = (const float*)d_in[6];
    const float* b1   = (const float*)d_in[7];
    const float* W2a  = (const float*)d_in[8];
    const float* b2a  = (const float*)d_in[9];
    const float* W2b  = (const float*)d_in[10];
    const float* b2b  = (const float*)d_in[11];
    const float* Wp   = (const float*)d_in[12];
    const float* bp   = (const float*)d_in[13];
    float* out = (float*)d_out;

    int n1 = in_sizes[0];
    int E1 = in_sizes[1] / 2;
    int np = in_sizes[2] / 2;
    int Q  = in_sizes[3] / 2;
    int E2 = in_sizes[4] / 2;

    int mx = (np > n1) ? np : n1;
    int Em = (E1 > E2) ? E1 : E2;

    k_zero    <<<(mx + 255) / 256, 256>>>(n1, np);
    k_count   <<<(Em + 255) / 256, 256>>>(e1, e2, E1, E2);
    k_dinv    <<<(mx + 255) / 256, 256>>>(n1, np);
    k_embed   <<<(n1 + 15) / 16, 128>>>(x, emb, W1, b1, n1);
    k_scatter1<<<(int)(((long long)E1 * 8 + 255) / 256), 256>>>(e1, E1);
    k_pair    <<<(int)(((long long)np * 8 + 255) / 256), 256>>>(pos, W2a, b2a, W2b, b2b, np);
    k_scatter2<<<(int)(((long long)E2 * 8 + 255) / 256), 256>>>(e2, E2);
    k_final   <<<(int)(((long long)Q  * 8 + 255) / 256), 256>>>(idx, Wp, bp, out, Q);
}

// round 9
// speedup vs baseline: 1.1160x; 1.1160x over previous
#include <cuda_runtime.h>

// Problem-shape maxima (compile-time array sizing; runtime uses in_sizes)
#define N1MAX 50000
#define NPMAX 200000
#define H2 32

// ---------------- scratch (static __device__, no allocation) ----------------
__device__ int   g_cnt1 [N1MAX];
__device__ int   g_cnt2f[NPMAX];
__device__ int   g_cnt2b[NPMAX];
__device__ __align__(16) float g_y1  [N1MAX * H2];   // xw1 * dinv1[src], conv1 messages
__device__ __align__(16) float g_out1[N1MAX * H2];   // conv1 accumulator
__device__ __align__(16) float g_ya  [NPMAX * H2];   // xwa * dinvf[src]
__device__ __align__(16) float g_yb  [NPMAX * H2];   // xwb * dinvb[src]
__device__ __align__(16) float g_outa[NPMAX * H2];
__device__ __align__(16) float g_outb[NPMAX * H2];

__device__ __forceinline__ void red_add_v4(float* addr, float4 v) {
    asm volatile("red.global.add.v4.f32 [%0], {%1,%2,%3,%4};"
                 :: "l"(addr), "f"(v.x), "f"(v.y), "f"(v.z), "f"(v.w)
                 : "memory");
}

// ---------------- 1. zero degree counters ----------------
__global__ void k_zero(int n1, int np) {
    int i = blockIdx.x * blockDim.x + threadIdx.x;
    if (i < np) { g_cnt2f[i] = 0; g_cnt2b[i] = 0; }
    if (i < n1) { g_cnt1[i] = 0; }
}

// ---------------- 2. degree counting (all three graphs in one pass) --------
__global__ void k_count(const int* __restrict__ e1, const int* __restrict__ e2,
                        int E1, int E2) {
    int i = blockIdx.x * blockDim.x + threadIdx.x;
    if (i < E1) atomicAdd(&g_cnt1[e1[E1 + i]], 1);          // conv1 dst = edge1[1]
    if (i < E2) {
        atomicAdd(&g_cnt2f[e2[E2 + i]], 1);                  // conv2a dst = ei2[1]
        atomicAdd(&g_cnt2b[e2[i]],      1);                  // conv2b dst = ei2[0]
    }
}

// ---------------- 3. embed gather + register-tiled GEMM (256 -> 32) ---------
// Block = 256 threads, 128 nodes/block. Each thread: 4 nodes x 4 cols tile.
// K chunked by 64: A chunk [128][68] (pad for banks) = 34 KB, W chunk 8 KB.
// Per k-quad: 4 A LDS.128 + 4 W LDS.128 -> 64 FFMA (1:8 LDS:FFMA).
__global__ __launch_bounds__(256) void k_embed(
    const int* __restrict__ x, const float* __restrict__ emb,
    const float* __restrict__ W1, const float* __restrict__ b1, int n1)
{
    __shared__ __align__(16) float Ws[64 * 32];       // 8 KB (per-chunk W)
    __shared__ __align__(16) float As[128 * 68];      // 34 KB, row stride 68

    int tid = threadIdx.x;
    int c4 = tid & 7;            // col group: cols c4*4 .. c4*4+3
    int ty = (tid >> 3) & 7;     // node lane within 32-node subtile
    int st = tid >> 6;           // subtile 0..3
    int nodeBase = blockIdx.x * 128;

    float acc[4][4];
    #pragma unroll
    for (int m = 0; m < 4; m++)
        #pragma unroll
        for (int c = 0; c < 4; c++) acc[m][c] = 0.f;

    int lcol = tid & 15;         // A-gather: float4 column within chunk
    int lrow = tid >> 4;         // A-gather: base row (16 rows per pass)

    for (int ch = 0; ch < 4; ch++) {
        // load W chunk: 64 rows x 32 cols
        #pragma unroll
        for (int i = 0; i < 8; i++)
            Ws[i * 256 + tid] = W1[ch * 2048 + i * 256 + tid];
        // gather A chunk: 128 rows x 16 float4
        #pragma unroll
        for (int pass = 0; pass < 8; pass++) {
            int r = lrow + pass * 16;
            int n = nodeBase + r;
            if (n < n1) {
                int xi = x[n];
                float4 v = reinterpret_cast<const float4*>(emb)
                               [(size_t)xi * 64 + ch * 16 + lcol];
                *reinterpret_cast<float4*>(&As[r * 68 + lcol * 4]) = v;
            }
        }
        __syncthreads();

        #pragma unroll
        for (int k4 = 0; k4 < 16; k4++) {
            float4 w0 = *reinterpret_cast<const float4*>(&Ws[(k4 * 4 + 0) * 32 + c4 * 4]);
            float4 w1 = *reinterpret_cast<const float4*>(&Ws[(k4 * 4 + 1) * 32 + c4 * 4]);
            float4 w2 = *reinterpret_cast<const float4*>(&Ws[(k4 * 4 + 2) * 32 + c4 * 4]);
            float4 w3 = *reinterpret_cast<const float4*>(&Ws[(k4 * 4 + 3) * 32 + c4 * 4]);
            #pragma unroll
            for (int m = 0; m < 4; m++) {
                int row = st * 32 + ty + 8 * m;
                float4 a = *reinterpret_cast<const float4*>(&As[row * 68 + k4 * 4]);
                acc[m][0] += a.x * w0.x + a.y * w1.x + a.z * w2.x + a.w * w3.x;
                acc[m][1] += a.x * w0.y + a.y * w1.y + a.z * w2.y + a.w * w3.y;
                acc[m][2] += a.x * w0.z + a.y * w1.z + a.z * w2.z + a.w * w3.z;
                acc[m][3] += a.x * w0.w + a.y * w1.w + a.z * w2.w + a.w * w3.w;
            }
        }
        __syncthreads();
    }

    float4 b4 = *reinterpret_cast<const float4*>(&b1[c4 * 4]);
    #pragma unroll
    for (int m = 0; m < 4; m++) {
        int node = nodeBase + st * 32 + ty + 8 * m;
        if (node < n1) {
            float dv = rsqrtf((float)(g_cnt1[node] + 1));
            float4 y = make_float4(acc[m][0] * dv, acc[m][1] * dv,
                                   acc[m][2] * dv, acc[m][3] * dv);
            *reinterpret_cast<float4*>(&g_y1[node * 32 + c4 * 4]) = y;
            *reinterpret_cast<float4*>(&g_out1[node * 32 + c4 * 4]) =
                make_float4(y.x * dv + b4.x, y.y * dv + b4.y,
                            y.z * dv + b4.z, y.w * dv + b4.w);
        }
    }
}

// ---------------- 4. conv1 edge scatter: 8 threads per edge, red.v4 ---------
__global__ void k_scatter1(const int* __restrict__ e1, int E1) {
    int tid = blockIdx.x * 256 + threadIdx.x;
    int e = tid >> 3, t = tid & 7;
    if (e >= E1) return;
    int s = e1[e], d = e1[E1 + e];
    float dv = rsqrtf((float)(g_cnt1[d] + 1));
    float4 y = *reinterpret_cast<const float4*>(&g_y1[s * 32 + t * 4]);
    red_add_v4(&g_out1[d * 32 + t * 4],
               make_float4(y.x * dv, y.y * dv, y.z * dv, y.w * dv));
}

// ---------------- 5. pair gather-multiply + fused 32x32 GEMVs ---------------
__global__ __launch_bounds__(256) void k_pair(
    const int* __restrict__ pos,
    const float* __restrict__ W2a, const float* __restrict__ b2a,
    const float* __restrict__ W2b, const float* __restrict__ b2b, int np)
{
    __shared__ __align__(16) float Was[1024];
    __shared__ __align__(16) float Wbs[1024];
    int tid = threadIdx.x;
    for (int i = tid; i < 1024; i += 256) { Was[i] = W2a[i]; Wbs[i] = W2b[i]; }
    __syncthreads();

    int g = blockIdx.x * 256 + tid;
    int m = g >> 3, t = g & 7;
    bool ok = (m < np);
    int p0 = 0, p1 = 0;
    if (ok) { p0 = pos[2 * m]; p1 = pos[2 * m + 1]; }

    float4 h0 = *reinterpret_cast<const float4*>(&g_out1[p0 * 32 + t * 4]);
    float4 h1 = *reinterpret_cast<const float4*>(&g_out1[p1 * 32 + t * 4]);
    float4 hp;
    hp.x = fmaxf(h0.x, 0.f) * fmaxf(h1.x, 0.f);
    hp.y = fmaxf(h0.y, 0.f) * fmaxf(h1.y, 0.f);
    hp.z = fmaxf(h0.z, 0.f) * fmaxf(h1.z, 0.f);
    hp.w = fmaxf(h0.w, 0.f) * fmaxf(h1.w, 0.f);

    float4 aa = make_float4(0.f, 0.f, 0.f, 0.f);
    float4 ab = make_float4(0.f, 0.f, 0.f, 0.f);
    #pragma unroll
    for (int src = 0; src < 8; src++) {
        float hv[4];
        hv[0] = __shfl_sync(0xffffffffu, hp.x, src, 8);
        hv[1] = __shfl_sync(0xffffffffu, hp.y, src, 8);
        hv[2] = __shfl_sync(0xffffffffu, hp.z, src, 8);
        hv[3] = __shfl_sync(0xffffffffu, hp.w, src, 8);
        #pragma unroll
        for (int kk = 0; kk < 4; kk++) {
            int k = src * 4 + kk;
            float4 wa = *reinterpret_cast<const float4*>(&Was[k * 32 + t * 4]);
            float4 wb = *reinterpret_cast<const float4*>(&Wbs[k * 32 + t * 4]);
            aa.x += hv[kk] * wa.x; aa.y += hv[kk] * wa.y;
            aa.z += hv[kk] * wa.z; aa.w += hv[kk] * wa.w;
            ab.x += hv[kk] * wb.x; ab.y += hv[kk] * wb.y;
            ab.z += hv[kk] * wb.z; ab.w += hv[kk] * wb.w;
        }
    }

    if (ok) {
        float da = rsqrtf((float)(g_cnt2f[m] + 1));
        float db = rsqrtf((float)(g_cnt2b[m] + 1));
        float4 ba4 = *reinterpret_cast<const float4*>(&b2a[t * 4]);
        float4 bb4 = *reinterpret_cast<const float4*>(&b2b[t * 4]);
        float4 ya = make_float4(aa.x * da, aa.y * da, aa.z * da, aa.w * da);
        float4 yb = make_float4(ab.x * db, ab.y * db, ab.z * db, ab.w * db);
        *reinterpret_cast<float4*>(&g_ya[m * 32 + t * 4]) = ya;
        *reinterpret_cast<float4*>(&g_yb[m * 32 + t * 4]) = yb;
        *reinterpret_cast<float4*>(&g_outa[m * 32 + t * 4]) =
            make_float4(ya.x * da + ba4.x, ya.y * da + ba4.y,
                        ya.z * da + ba4.z, ya.w * da + ba4.w);
        *reinterpret_cast<float4*>(&g_outb[m * 32 + t * 4]) =
            make_float4(yb.x * db + bb4.x, yb.y * db + bb4.y,
                        yb.z * db + bb4.z, yb.w * db + bb4.w);
    }
}

// ---------------- 6. conv2 (fwd + reversed) edge scatter --------------------
__global__ void k_scatter2(const int* __restrict__ e2, int E2) {
    int tid = blockIdx.x * 256 + threadIdx.x;
    int e = tid >> 3, t = tid & 7;
    if (e >= E2) return;
    int u = e2[e], v = e2[E2 + e];
    // conv2a: src=u, dst=v (deg over ei2[1])
    float dvf = rsqrtf((float)(g_cnt2f[v] + 1));
    float4 ya = *reinterpret_cast<const float4*>(&g_ya[u * 32 + t * 4]);
    red_add_v4(&g_outa[v * 32 + t * 4],
               make_float4(ya.x * dvf, ya.y * dvf, ya.z * dvf, ya.w * dvf));
    // conv2b: src=v, dst=u (deg over ei2[0])
    float dub = rsqrtf((float)(g_cnt2b[u] + 1));
    float4 yb = *reinterpret_cast<const float4*>(&g_yb[v * 32 + t * 4]);
    red_add_v4(&g_outb[u * 32 + t * 4],
               make_float4(yb.x * dub, yb.y * dub, yb.z * dub, yb.w * dub));
}

// ---------------- 7. final: gather idx, even*odd, dot with Wp ---------------
__global__ void k_final(const int* __restrict__ idx,
                        const float* __restrict__ Wp, const float* __restrict__ bp,
                        float* __restrict__ out, int Q)
{
    int tid = blockIdx.x * 256 + threadIdx.x;
    int q = tid >> 3, t = tid & 7;
    bool ok = (q < Q);
    int i0 = 0, i1 = 0;
    if (ok) { i0 = idx[2 * q]; i1 = idx[2 * q + 1]; }

    float4 a0 = *reinterpret_cast<const float4*>(&g_outa[i0 * 32 + t * 4]);
    float4 b0 = *reinterpret_cast<const float4*>(&g_outb[i0 * 32 + t * 4]);
    float4 a1 = *reinterpret_cast<const float4*>(&g_outa[i1 * 32 + t * 4]);
    float4 b1 = *reinterpret_cast<const float4*>(&g_outb[i1 * 32 + t * 4]);

    float4 h0, h1;
    h0.x = fmaxf(a0.x, 0.f) + fmaxf(b0.x, 0.f);
    h0.y = fmaxf(a0.y, 0.f) + fmaxf(b0.y, 0.f);
    h0.z = fmaxf(a0.z, 0.f) + fmaxf(b0.z, 0.f);
    h0.w = fmaxf(a0.w, 0.f) + fmaxf(b0.w, 0.f);
    h1.x = fmaxf(a1.x, 0.f) + fmaxf(b1.x, 0.f);
    h1.y = fmaxf(a1.y, 0.f) + fmaxf(b1.y, 0.f);
    h1.z = fmaxf(a1.z, 0.f) + fmaxf(b1.z, 0.f);
    h1.w = fmaxf(a1.w, 0.f) + fmaxf(b1.w, 0.f);

    float4 wp4 = *reinterpret_cast<const float4*>(&Wp[t * 4]);
    float s = h0.x * h1.x * wp4.x + h0.y * h1.y * wp4.y
            + h0.z * h1.z * wp4.z + h0.w * h1.w * wp4.w;
    s += __shfl_xor_sync(0xffffffffu, s, 1, 8);
    s += __shfl_xor_sync(0xffffffffu, s, 2, 8);
    s += __shfl_xor_sync(0xffffffffu, s, 4, 8);
    if (ok && t == 0) out[q] = s + __ldg(bp);
}

// ---------------- launch ----------------------------------------------------
extern "C" void kernel_launch(void* const* d_in, const int* in_sizes, int n_in,
                              void* d_out, int out_size) {
    const int*   x    = (const int*)  d_in[0];
    const int*   e1   = (const int*)  d_in[1];
    const int*   pos  = (const int*)  d_in[2];
    const int*   idx  = (const int*)  d_in[3];
    const int*   e2   = (const int*)  d_in[4];
    const float* emb  = (const float*)d_in[5];
    const float* W1   = (const float*)d_in[6];
    const float* b1   = (const float*)d_in[7];
    const float* W2a  = (const float*)d_in[8];
    const float* b2a  = (const float*)d_in[9];
    const float* W2b  = (const float*)d_in[10];
    const float* b2b  = (const float*)d_in[11];
    const float* Wp   = (const float*)d_in[12];
    const float* bp   = (const float*)d_in[13];
    float* out = (float*)d_out;

    int n1 = in_sizes[0];
    int E1 = in_sizes[1] / 2;
    int np = in_sizes[2] / 2;
    int Q  = in_sizes[3] / 2;
    int E2 = in_sizes[4] / 2;

    int mx = (np > n1) ? np : n1;
    int Em = (E1 > E2) ? E1 : E2;

    k_zero    <<<(mx + 255) / 256, 256>>>(n1, np);
    k_count   <<<(Em + 255) / 256, 256>>>(e1, e2, E1, E2);
    k_embed   <<<(n1 + 127) / 128, 256>>>(x, emb, W1, b1, n1);
    k_scatter1<<<(int)(((long long)E1 * 8 + 255) / 256), 256>>>(e1, E1);
    k_pair    <<<(int)(((long long)np * 8 + 255) / 256), 256>>>(pos, W2a, b2a, W2b, b2b, np);
    k_scatter2<<<(int)(((long long)E2 * 8 + 255) / 256), 256>>>(e2, E2);
    k_final   <<<(int)(((long long)Q  * 8 + 255) / 256), 256>>>(idx, Wp, bp, out, Q);
}

// round 12
// speedup vs baseline: 1.1435x; 1.0246x over previous
#include <cuda_runtime.h>

// Problem-shape maxima (compile-time array sizing; runtime uses in_sizes)
#define N1MAX 50000
#define NPMAX 200000
#define H2 32

// ---------------- scratch (static __device__, no allocation) ----------------
__device__ int   g_cnt1 [N1MAX];
__device__ int   g_cnt2f[NPMAX];
__device__ int   g_cnt2b[NPMAX];
__device__ float g_dinv1[N1MAX];
__device__ float g_dinvf[NPMAX];
__device__ float g_dinvb[NPMAX];
__device__ __align__(16) float g_y1  [N1MAX * H2];   // xw1 * dinv1[src]  (conv1 messages)
__device__ __align__(16) float g_out1[N1MAX * H2];   // raw acc: y1[d] + sum y1[src]
__device__ __align__(16) float g_ya  [NPMAX * H2];   // xwa * dinvf[src]
__device__ __align__(16) float g_yb  [NPMAX * H2];   // xwb * dinvb[src]
__device__ __align__(16) float g_outa[NPMAX * H2];   // raw acc for conv2a
__device__ __align__(16) float g_outb[NPMAX * H2];   // raw acc for conv2b

__device__ __forceinline__ void red_add_v4(float* addr, float4 v) {
    asm volatile("red.global.add.v4.f32 [%0], {%1,%2,%3,%4};"
                 :: "l"(addr), "f"(v.x), "f"(v.y), "f"(v.z), "f"(v.w)
                 : "memory");
}

// ---------------- 1. zero degree counters ----------------
__global__ void k_zero(int n1, int np) {
    int i = blockIdx.x * blockDim.x + threadIdx.x;
    if (i < np) { g_cnt2f[i] = 0; g_cnt2b[i] = 0; }
    if (i < n1) { g_cnt1[i] = 0; }
}

// ---------------- 2. degree counting (all three graphs in one pass) --------
__global__ void k_count(const int* __restrict__ e1, const int* __restrict__ e2,
                        int E1, int E2) {
    int i = blockIdx.x * blockDim.x + threadIdx.x;
    if (i < E1) atomicAdd(&g_cnt1[e1[E1 + i]], 1);          // conv1 dst = edge1[1]
    if (i < E2) {
        atomicAdd(&g_cnt2f[e2[E2 + i]], 1);                  // conv2a dst = ei2[1]
        atomicAdd(&g_cnt2b[e2[i]],      1);                  // conv2b dst = ei2[0]
    }
}

// ---------------- 3. rsqrt degrees ONCE (deg = count + 1 self-loop) ---------
__global__ void k_dinv(int n1, int np) {
    int i = blockIdx.x * blockDim.x + threadIdx.x;
    if (i < np) {
        g_dinvf[i] = rsqrtf((float)(g_cnt2f[i] + 1));
        g_dinvb[i] = rsqrtf((float)(g_cnt2b[i] + 1));
    }
    if (i < n1) g_dinv1[i] = rsqrtf((float)(g_cnt1[i] + 1));
}

// ---------------- 4. embed gather + register-tiled GEMM (256 -> 32) ---------
// Block = 256 threads, 128 nodes/block. Each thread: 4 nodes x 4 cols tile.
__global__ __launch_bounds__(256) void k_embed(
    const int* __restrict__ x, const float* __restrict__ emb,
    const float* __restrict__ W1, int n1)
{
    __shared__ __align__(16) float Ws[64 * 32];       // 8 KB (per-chunk W)
    __shared__ __align__(16) float As[128 * 68];      // 34 KB, row stride 68

    int tid = threadIdx.x;
    int c4 = tid & 7;            // col group: cols c4*4 .. c4*4+3
    int ty = (tid >> 3) & 7;     // node lane within 32-node subtile
    int st = tid >> 6;           // subtile 0..3
    int nodeBase = blockIdx.x * 128;

    float acc[4][4];
    #pragma unroll
    for (int m = 0; m < 4; m++)
        #pragma unroll
        for (int c = 0; c < 4; c++) acc[m][c] = 0.f;

    int lcol = tid & 15;         // A-gather: float4 column within chunk
    int lrow = tid >> 4;         // A-gather: base row (16 rows per pass)

    for (int ch = 0; ch < 4; ch++) {
        #pragma unroll
        for (int i = 0; i < 8; i++)
            Ws[i * 256 + tid] = W1[ch * 2048 + i * 256 + tid];
        #pragma unroll
        for (int pass = 0; pass < 8; pass++) {
            int r = lrow + pass * 16;
            int n = nodeBase + r;
            if (n < n1) {
                int xi = x[n];
                float4 v = reinterpret_cast<const float4*>(emb)
                               [(size_t)xi * 64 + ch * 16 + lcol];
                *reinterpret_cast<float4*>(&As[r * 68 + lcol * 4]) = v;
            }
        }
        __syncthreads();

        #pragma unroll
        for (int k4 = 0; k4 < 16; k4++) {
            float4 w0 = *reinterpret_cast<const float4*>(&Ws[(k4 * 4 + 0) * 32 + c4 * 4]);
            float4 w1 = *reinterpret_cast<const float4*>(&Ws[(k4 * 4 + 1) * 32 + c4 * 4]);
            float4 w2 = *reinterpret_cast<const float4*>(&Ws[(k4 * 4 + 2) * 32 + c4 * 4]);
            float4 w3 = *reinterpret_cast<const float4*>(&Ws[(k4 * 4 + 3) * 32 + c4 * 4]);
            #pragma unroll
            for (int m = 0; m < 4; m++) {
                int row = st * 32 + ty + 8 * m;
                float4 a = *reinterpret_cast<const float4*>(&As[row * 68 + k4 * 4]);
                acc[m][0] += a.x * w0.x + a.y * w1.x + a.z * w2.x + a.w * w3.x;
                acc[m][1] += a.x * w0.y + a.y * w1.y + a.z * w2.y + a.w * w3.y;
                acc[m][2] += a.x * w0.z + a.y * w1.z + a.z * w2.z + a.w * w3.z;
                acc[m][3] += a.x * w0.w + a.y * w1.w + a.z * w2.w + a.w * w3.w;
            }
        }
        __syncthreads();
    }

    #pragma unroll
    for (int m = 0; m < 4; m++) {
        int node = nodeBase + st * 32 + ty + 8 * m;
        if (node < n1) {
            float dv = g_dinv1[node];
            float4 y = make_float4(acc[m][0] * dv, acc[m][1] * dv,
                                   acc[m][2] * dv, acc[m][3] * dv);
            *reinterpret_cast<float4*>(&g_y1  [node * 32 + c4 * 4]) = y;
            *reinterpret_cast<float4*>(&g_out1[node * 32 + c4 * 4]) = y;  // self-loop init
        }
    }
}

// ---------------- 5. conv1 edge scatter: PURE data movement -----------------
// acc[d] += y1[s]; dst-side dinv + bias applied later in k_pair.
__global__ void k_scatter1(const int* __restrict__ e1, int E1) {
    int tid = blockIdx.x * 256 + threadIdx.x;
    int e = tid >> 3, t = tid & 7;
    if (e >= E1) return;
    int s = e1[e], d = e1[E1 + e];
    float4 y = *reinterpret_cast<const float4*>(&g_y1[s * 32 + t * 4]);
    red_add_v4(&g_out1[d * 32 + t * 4], y);
}

// ---------------- 6. pair gather-multiply + fused 32x32 GEMVs ---------------
// Applies conv1's deferred dst scaling: h = relu(acc * dinv1 + b1).
__global__ __launch_bounds__(256) void k_pair(
    const int* __restrict__ pos,
    const float* __restrict__ W2a, const float* __restrict__ b1v,
    const float* __restrict__ W2b, int np)
{
    __shared__ __align__(16) float Was[1024];
    __shared__ __align__(16) float Wbs[1024];
    int tid = threadIdx.x;
    for (int i = tid; i < 1024; i += 256) { Was[i] = W2a[i]; Wbs[i] = W2b[i]; }
    __syncthreads();

    int g = blockIdx.x * 256 + tid;
    int m = g >> 3, t = g & 7;
    bool ok = (m < np);
    int p0 = 0, p1 = 0;
    if (ok) { p0 = pos[2 * m]; p1 = pos[2 * m + 1]; }

    float dv0 = g_dinv1[p0], dv1 = g_dinv1[p1];
    float4 b14 = *reinterpret_cast<const float4*>(&b1v[t * 4]);
    float4 h0 = *reinterpret_cast<const float4*>(&g_out1[p0 * 32 + t * 4]);
    float4 h1 = *reinterpret_cast<const float4*>(&g_out1[p1 * 32 + t * 4]);
    float4 hp;
    hp.x = fmaxf(h0.x * dv0 + b14.x, 0.f) * fmaxf(h1.x * dv1 + b14.x, 0.f);
    hp.y = fmaxf(h0.y * dv0 + b14.y, 0.f) * fmaxf(h1.y * dv1 + b14.y, 0.f);
    hp.z = fmaxf(h0.z * dv0 + b14.z, 0.f) * fmaxf(h1.z * dv1 + b14.z, 0.f);
    hp.w = fmaxf(h0.w * dv0 + b14.w, 0.f) * fmaxf(h1.w * dv1 + b14.w, 0.f);

    float4 aa = make_float4(0.f, 0.f, 0.f, 0.f);
    float4 ab = make_float4(0.f, 0.f, 0.f, 0.f);
    #pragma unroll
    for (int src = 0; src < 8; src++) {
        float hv[4];
        hv[0] = __shfl_sync(0xffffffffu, hp.x, src, 8);
        hv[1] = __shfl_sync(0xffffffffu, hp.y, src, 8);
        hv[2] = __shfl_sync(0xffffffffu, hp.z, src, 8);
        hv[3] = __shfl_sync(0xffffffffu, hp.w, src, 8);
        #pragma unroll
        for (int kk = 0; kk < 4; kk++) {
            int k = src * 4 + kk;
            float4 wa = *reinterpret_cast<const float4*>(&Was[k * 32 + t * 4]);
            float4 wb = *reinterpret_cast<const float4*>(&Wbs[k * 32 + t * 4]);
            aa.x += hv[kk] * wa.x; aa.y += hv[kk] * wa.y;
            aa.z += hv[kk] * wa.z; aa.w += hv[kk] * wa.w;
            ab.x += hv[kk] * wb.x; ab.y += hv[kk] * wb.y;
            ab.z += hv[kk] * wb.z; ab.w += hv[kk] * wb.w;
        }
    }

    if (ok) {
        float da = g_dinvf[m], db = g_dinvb[m];
        float4 ya = make_float4(aa.x * da, aa.y * da, aa.z * da, aa.w * da);
        float4 yb = make_float4(ab.x * db, ab.y * db, ab.z * db, ab.w * db);
        *reinterpret_cast<float4*>(&g_ya  [m * 32 + t * 4]) = ya;
        *reinterpret_cast<float4*>(&g_yb  [m * 32 + t * 4]) = yb;
        *reinterpret_cast<float4*>(&g_outa[m * 32 + t * 4]) = ya;  // self-loop init
        *reinterpret_cast<float4*>(&g_outb[m * 32 + t * 4]) = yb;  // self-loop init
    }
}

// ---------------- 7. conv2 (fwd + reversed) edge scatter: pure movement -----
__global__ void k_scatter2(const int* __restrict__ e2, int E2) {
    int tid = blockIdx.x * 256 + threadIdx.x;
    int e = tid >> 3, t = tid & 7;
    if (e >= E2) return;
    int u = e2[e], v = e2[E2 + e];
    float4 ya = *reinterpret_cast<const float4*>(&g_ya[u * 32 + t * 4]);
    red_add_v4(&g_outa[v * 32 + t * 4], ya);     // conv2a: u -> v
    float4 yb = *reinterpret_cast<const float4*>(&g_yb[v * 32 + t * 4]);
    red_add_v4(&g_outb[u * 32 + t * 4], yb);     // conv2b: v -> u
}

// ---------------- 8. final: deferred conv2 scaling + even*odd + dot Wp ------
__global__ void k_final(const int* __restrict__ idx,
                        const float* __restrict__ b2a, const float* __restrict__ b2b,
                        const float* __restrict__ Wp, const float* __restrict__ bp,
                        float* __restrict__ out, int Q)
{
    int tid = blockIdx.x * 256 + threadIdx.x;
    int q = tid >> 3, t = tid & 7;
    bool ok = (q < Q);
    int i0 = 0, i1 = 0;
    if (ok) { i0 = idx[2 * q]; i1 = idx[2 * q + 1]; }

    float f0 = g_dinvf[i0], g0 = g_dinvb[i0];
    float f1 = g_dinvf[i1], g1 = g_dinvb[i1];
    float4 ba = *reinterpret_cast<const float4*>(&b2a[t * 4]);
    float4 bb = *reinterpret_cast<const float4*>(&b2b[t * 4]);

    float4 a0 = *reinterpret_cast<const float4*>(&g_outa[i0 * 32 + t * 4]);
    float4 c0 = *reinterpret_cast<const float4*>(&g_outb[i0 * 32 + t * 4]);
    float4 a1 = *reinterpret_cast<const float4*>(&g_outa[i1 * 32 + t * 4]);
    float4 c1 = *reinterpret_cast<const float4*>(&g_outb[i1 * 32 + t * 4]);

    float4 h0, h1;
    h0.x = fmaxf(a0.x * f0 + ba.x, 0.f) + fmaxf(c0.x * g0 + bb.x, 0.f);
    h0.y = fmaxf(a0.y * f0 + ba.y, 0.f) + fmaxf(c0.y * g0 + bb.y, 0.f);
    h0.z = fmaxf(a0.z * f0 + ba.z, 0.f) + fmaxf(c0.z * g0 + bb.z, 0.f);
    h0.w = fmaxf(a0.w * f0 + ba.w, 0.f) + fmaxf(c0.w * g0 + bb.w, 0.f);
    h1.x = fmaxf(a1.x * f1 + ba.x, 0.f) + fmaxf(c1.x * g1 + bb.x, 0.f);
    h1.y = fmaxf(a1.y * f1 + ba.y, 0.f) + fmaxf(c1.y * g1 + bb.y, 0.f);
    h1.z = fmaxf(a1.z * f1 + ba.z, 0.f) + fmaxf(c1.z * g1 + bb.z, 0.f);
    h1.w = fmaxf(a1.w * f1 + ba.w, 0.f) + fmaxf(c1.w * g1 + bb.w, 0.f);

    float4 wp4 = *reinterpret_cast<const float4*>(&Wp[t * 4]);
    float s = h0.x * h1.x * wp4.x + h0.y * h1.y * wp4.y
            + h0.z * h1.z * wp4.z + h0.w * h1.w * wp4.w;
    s += __shfl_xor_sync(0xffffffffu, s, 1, 8);
    s += __shfl_xor_sync(0xffffffffu, s, 2, 8);
    s += __shfl_xor_sync(0xffffffffu, s, 4, 8);
    if (ok && t == 0) out[q] = s + __ldg(bp);
}

// ---------------- launch ----------------------------------------------------
extern "C" void kernel_launch(void* const* d_in, const int* in_sizes, int n_in,
                              void* d_out, int out_size) {
    const int*   x    = (const int*)  d_in[0];
    const int*   e1   = (const int*)  d_in[1];
    const int*   pos  = (const int*)  d_in[2];
    const int*   idx  = (const int*)  d_in[3];
    const int*   e2   = (const int*)  d_in[4];
    const float* emb  = (const float*)d_in[5];
    const float* W1   = (const float*)d_in[6];
    const float* b1   = (const float*)d_in[7];
    const float* W2a  = (const float*)d_in[8];
    const float* b2a  = (const float*)d_in[9];
    const float* W2b  = (const float*)d_in[10];
    const float* b2b  = (const float*)d_in[11];
    const float* Wp   = (const float*)d_in[12];
    const float* bp   = (const float*)d_in[13];
    float* out = (float*)d_out;

    int n1 = in_sizes[0];
    int E1 = in_sizes[1] / 2;
    int np = in_sizes[2] / 2;
    int Q  = in_sizes[3] / 2;
    int E2 = in_sizes[4] / 2;

    int mx = (np > n1) ? np : n1;
    int Em = (E1 > E2) ? E1 : E2;

    k_zero    <<<(mx + 255) / 256, 256>>>(n1, np);
    k_count   <<<(Em + 255) / 256, 256>>>(e1, e2, E1, E2);
    k_dinv    <<<(mx + 255) / 256, 256>>>(n1, np);
    k_embed   <<<(n1 + 127) / 128, 256>>>(x, emb, W1, n1);
    k_scatter1<<<(int)(((long long)E1 * 8 + 255) / 256), 256>>>(e1, E1);
    k_pair    <<<(int)(((long long)np * 8 + 255) / 256), 256>>>(pos, W2a, b1, W2b, np);
    k_scatter2<<<(int)(((long long)E2 * 8 + 255) / 256), 256>>>(e2, E2);
    k_final   <<<(int)(((long long)Q  * 8 + 255) / 256), 256>>>(idx, b2a, b2b, Wp, bp, out, Q);
}